// round 6
// baseline (speedup 1.0000x reference)
#include <cuda_runtime.h>
#include <math.h>
#include <float.h>

#define BB 64
#define NN 32768
#define CC 2
#define KK 10
#define QT 16                // chunks per batch row (one block each)
#define CHUNK (NN / QT)      // 2048 columns per block
#define SEG 1024             // columns per smem tile
#define NTILE (CHUNK / SEG)  // 2
#define NWARP 10
#define NTHR (NWARP * 32)    // 320
#define FULLM 0xffffffffu
#define MAXC 0x7fffffff

// fast sigmoid for candidate scanning (2 MUFU + 3 ops)
static __device__ __forceinline__ float fsig(float x) {
    return __fdividef(1.0f, 1.0f + __expf(-x));
}
// accurate versions for the final loss terms (640 evaluations, cheap)
static __device__ __forceinline__ float sigmoidf_(float x) {
    return 1.0f / (1.0f + expf(-x));
}
static __device__ __forceinline__ float softplusf_(float x) {
    return fmaxf(x, 0.0f) + log1pf(expf(-fabsf(x)));
}

// partial top-10 per (batch, row, chunk)
__device__ float g_part_val[BB * KK * QT * KK];
__device__ int   g_part_col[BB * KK * QT * KK];
// per-batch loss partials
__device__ float g_bpart[BB];
__device__ float g_bm[BB];

// ---------------------------------------------------------------------------
// Warp-collective: merge smem candidate buffer (cnt <= 64) + current
// distributed top-10 (lane j < 10 holds j-th best) -> new top-10 + tau.
// Lexicographic (val, col) ascending == jnp.argmin flat-index tie order.
// ---------------------------------------------------------------------------
static __device__ __forceinline__ void merge10(float& lv, int& lc, float& tau,
                                               int cnt, const float* bv,
                                               const int* bc, int lane) {
    __syncwarp();
    float v0 = (lane < cnt) ? bv[lane] : FLT_MAX;
    int   c0 = (lane < cnt) ? bc[lane] : MAXC;
    float v1 = (lane + 32 < cnt) ? bv[lane + 32] : FLT_MAX;
    int   c1 = (lane + 32 < cnt) ? bc[lane + 32] : MAXC;
    float v2 = lv;  // lanes >= 10 hold FLT_MAX
    int   c2 = lc;
    float nv = FLT_MAX; int nc = MAXC;
#pragma unroll
    for (int r = 0; r < KK; r++) {
        float mv = v0; int mc = c0; int sl = 0;
        if (v1 < mv || (v1 == mv && c1 < mc)) { mv = v1; mc = c1; sl = 1; }
        if (v2 < mv || (v2 == mv && c2 < mc)) { mv = v2; mc = c2; sl = 2; }
        int src = lane;
#pragma unroll
        for (int o = 16; o; o >>= 1) {
            float ov = __shfl_xor_sync(FULLM, mv, o);
            int   oc = __shfl_xor_sync(FULLM, mc, o);
            int   os = __shfl_xor_sync(FULLM, src, o);
            if (ov < mv || (ov == mv && oc < mc)) { mv = ov; mc = oc; src = os; }
        }
        if (lane == src) {  // consume winning slot
            if (sl == 0)      { v0 = FLT_MAX; c0 = MAXC; }
            else if (sl == 1) { v1 = FLT_MAX; c1 = MAXC; }
            else              { v2 = FLT_MAX; c2 = MAXC; }
        }
        if (lane == r) { nv = mv; nc = mc; }
    }
    lv = nv; lc = nc;
    tau = __shfl_sync(FULLM, lv, KK - 1);
}

// ---------------------------------------------------------------------------
// Kernel A: fused features (fast sigmoid) + tau-gated buffered top-10.
// Block = (batch, chunk); 10 warps all fill the tile, warp w scans row w.
// ---------------------------------------------------------------------------
__global__ __launch_bounds__(NTHR, 5) void fused_topk_kernel(
        const float* __restrict__ ps,
        const float* __restrict__ pe,
        const float* __restrict__ pcl,
        const float* __restrict__ gt) {
    __shared__ float4 feat[SEG];          // 16KB: (s, e, h0, h1)
    __shared__ float  bufv[NWARP][64];
    __shared__ int    bufc[NWARP][64];

    int b = blockIdx.x >> 4;
    int chunk = blockIdx.x & (QT - 1);
    int cbase = chunk * CHUNK;
    int w = threadIdx.x >> 5;
    int lane = threadIdx.x & 31;

    const float* g = gt + (size_t)(b * KK + w) * 3;
    float fs = g[0], fe = g[1], cl = g[2];
    bool present = !((fs != fs) || (fe != fe) || (cl != cl));
    bool cls0 = true;
    float ms = 0.0f, me = 0.0f;
    if (present) {
        int ci = (int)cl;
        ci = ci < 0 ? 0 : (ci > CC - 1 ? CC - 1 : ci);
        cls0 = (ci == 0);
        ms = -2.0f * fs;
        me = -2.0f * fe;
    }

    float lv = FLT_MAX; int lc = MAXC;   // lane j<10: j-th best (shifted val)
    float tau = FLT_MAX;
    int cnt = 0;

    const float2* pcl2 = reinterpret_cast<const float2*>(pcl);

    for (int t = 0; t < NTILE; t++) {
        int colbase = cbase + t * SEG;
        size_t gb = (size_t)b * NN + colbase;

        // ---- feature phase: all 320 threads, fast sigmoid ----
        for (int i = threadIdx.x; i < SEG; i += NTHR) {
            float s = fsig(ps[gb + i]);
            float e = fsig(pe[gb + i]);
            float2 l = pcl2[gb + i];
            float c0 = fsig(l.x);
            float c1 = fsig(l.y);
            float base = fmaf(s, s, fmaf(e, e, fmaf(c0, c0, fmaf(c1, c1, 1.0f))));
            feat[i] = make_float4(s, e, base - 2.0f * c0, base - 2.0f * c1);
        }
        __syncthreads();

        // ---- scan phase: warp w scans row w ----
        if (present) {
#pragma unroll 4
            for (int r = 0; r < SEG / 32; r++) {
                int i = r * 32 + lane;
                float4 f = feat[i];
                float v = fmaf(f.x, ms, fmaf(f.y, me, cls0 ? f.z : f.w));
                unsigned bal = __ballot_sync(FULLM, v <= tau);
                if (bal) {
                    if (v <= tau) {
                        int pos = cnt + __popc(bal & ((1u << lane) - 1u));
                        bufv[w][pos] = v;
                        bufc[w][pos] = colbase + i;
                    }
                    cnt += __popc(bal);
                    if (cnt > 32) {
                        merge10(lv, lc, tau, cnt, bufv[w], bufc[w], lane);
                        cnt = 0;
                    }
                }
            }
        }
        __syncthreads();
    }

    if (present && cnt) merge10(lv, lc, tau, cnt, bufv[w], bufc[w], lane);

    if (lane < KK) {
        int ob = ((b * KK + w) * QT + chunk) * KK + lane;
        if (present) {
            g_part_val[ob] = lv + fmaf(fs, fs, fe * fe);  // restore row constant
            g_part_col[ob] = lc;
        } else {
            g_part_val[ob] = 1.0e6f;                      // sentinel (never valid)
            g_part_col[ob] = cbase + lane;
        }
    }
}

// ---------------------------------------------------------------------------
// Kernel B: per-batch merge (warp per row, 160 partials) + warp-parallel
// greedy match + exact losses.
// ---------------------------------------------------------------------------
__global__ __launch_bounds__(NTHR) void merge_match_kernel(
        const float* __restrict__ ps,
        const float* __restrict__ pe,
        const float* __restrict__ pcl,
        const float* __restrict__ pcf,
        const float* __restrict__ gt) {
    __shared__ float sval[KK * KK];
    __shared__ int   scol[KK * KK];
    __shared__ float s_fs[KK], s_fe[KK];
    __shared__ int   s_cli[KK];
    __shared__ int   s_mk[KK], s_mcol[KK];
    __shared__ int   s_nm;
    __shared__ float s_loss[KK];

    int b = blockIdx.x;
    int w = threadIdx.x >> 5;
    int lane = threadIdx.x & 31;

    // ---- merge 160 partials (5 slots/lane) -> sorted top-10 per row ----
    {
        int ib = (b * KK + w) * (QT * KK);  // 160 entries
        float v[5]; int c[5];
#pragma unroll
        for (int j = 0; j < 5; j++) {
            v[j] = g_part_val[ib + j * 32 + lane];
            c[j] = g_part_col[ib + j * 32 + lane];
        }
#pragma unroll
        for (int r = 0; r < KK; r++) {
            float mv = v[0]; int mc = c[0]; int sl = 0;
#pragma unroll
            for (int j = 1; j < 5; j++) {
                if (v[j] < mv || (v[j] == mv && c[j] < mc)) { mv = v[j]; mc = c[j]; sl = j; }
            }
            int src = lane;
#pragma unroll
            for (int o = 16; o; o >>= 1) {
                float ov = __shfl_xor_sync(FULLM, mv, o);
                int   oc = __shfl_xor_sync(FULLM, mc, o);
                int   os = __shfl_xor_sync(FULLM, src, o);
                if (ov < mv || (ov == mv && oc < mc)) { mv = ov; mc = oc; src = os; }
            }
            if (lane == src) { v[sl] = FLT_MAX; c[sl] = MAXC; }
            if (lane == 0) { sval[w * KK + r] = mv; scol[w * KK + r] = mc; }
        }
    }
    if (threadIdx.x < KK) {
        const float* g = gt + (size_t)(b * KK + threadIdx.x) * 3;
        float a = g[0], c = g[1], d = g[2];
        bool pres = !((a != a) || (c != c) || (d != d));
        s_fs[threadIdx.x] = (a != a) ? 0.0f : a;
        s_fe[threadIdx.x] = (c != c) ? 0.0f : c;
        d = (d != d) ? 0.0f : d;
        int ci = (int)d;
        ci = ci < 0 ? 0 : (ci > CC - 1 ? CC - 1 : ci);
        s_cli[threadIdx.x] = pres ? ci : -1;   // -1 = absent
    }
    __syncthreads();

    // ---- warp-parallel greedy match (warp 0, lane k owns row k) ----
    // Absent rows (cost==VL everywhere) are provably matched after all present
    // rows (real costs << VL), contribute zero loss, and cannot steal columns
    // from present rows -> skip them entirely (same as prior rounds).
    if (w == 0) {
        bool active = (lane < KK) && (s_cli[lane] >= 0);
        int ptr = 0;
        int usedc[KK];
        int nused = 0;
        int nm = 0;
        for (int it = 0; it < KK; it++) {
            float myv = FLT_MAX; int mycol = MAXC;
            if (active) {
                while (ptr < KK) {
                    int col = scol[lane * KK + ptr];
                    bool isused = false;
                    for (int u = 0; u < nused; u++) isused |= (usedc[u] == col);
                    if (!isused) { myv = sval[lane * KK + ptr]; mycol = col; break; }
                    ptr++;
                }
            }
            // lex argmin over (val, row); within-row col order from sorted list
            float bvv = myv; int brow = lane; int bcol = mycol;
#pragma unroll
            for (int o = 16; o; o >>= 1) {
                float ov = __shfl_xor_sync(FULLM, bvv, o);
                int   orw = __shfl_xor_sync(FULLM, brow, o);
                int   ocl = __shfl_xor_sync(FULLM, bcol, o);
                if (ov < bvv || (ov == bvv && orw < brow)) { bvv = ov; brow = orw; bcol = ocl; }
            }
            if (bvv == FLT_MAX) break;          // no active rows remain
            usedc[nused++] = bcol;
            if (lane == brow) active = false;
            if (bvv < 0.5e6f) {                  // valid = val < VL/2
                if (lane == 0) { s_mk[nm] = brow; s_mcol[nm] = bcol; }
                nm++;
            }
        }
        if (lane == 0) s_nm = nm;
    }
    __syncthreads();

    // ---- exact loss terms in parallel (threads 0..nm-1) ----
    int nm = s_nm;
    if (threadIdx.x < KK) {
        float part = 0.0f;
        if (threadIdx.x < nm) {
            int k = s_mk[threadIdx.x];
            int col = s_mcol[threadIdx.x];
            size_t idx = (size_t)b * NN + col;
            float ss = sigmoidf_(ps[idx]);
            float se = sigmoidf_(pe[idx]);
            float gs = s_fs[k], ge = s_fe[k];
            float dls = ss - gs, dle = se - ge;
            part = dls * dls + dle * dle;                           // loc
            float l0 = pcl[idx * 2], l1 = pcl[idx * 2 + 1];
            part += (s_cli[k] == 0) ? (softplusf_(-l0) + softplusf_(l1))
                                    : (softplusf_(l0) + softplusf_(-l1));  // class
            float a1 = fminf(ss, se), b1 = fmaxf(ss, se);
            float a2 = fminf(gs, ge), b2 = fmaxf(gs, ge);
            float inter = fmaxf(0.0f, fminf(b1, b2) - fmaxf(a1, a2));
            float uni = fmaxf(1e-8f, fmaxf(b1, b2) - fminf(a1, a2));
            float iou = inter / uni;
            float dcf = sigmoidf_(pcf[idx]) - iou;
            part += dcf * dcf;                                      // conf
        }
        s_loss[threadIdx.x] = part;
    }
    __syncthreads();

    if (threadIdx.x == 0) {
        float tot = 0.0f;
#pragma unroll
        for (int j = 0; j < KK; j++) tot += s_loss[j];
        g_bpart[b] = tot;
        g_bm[b] = (float)nm;
    }
}

// ---------------------------------------------------------------------------
// Kernel C: final reduction over batches
// ---------------------------------------------------------------------------
__global__ void finalize_kernel(float* __restrict__ out) {
    __shared__ float sP[BB], sM[BB];
    sP[threadIdx.x] = g_bpart[threadIdx.x];
    sM[threadIdx.x] = g_bm[threadIdx.x];
    __syncthreads();
    for (int st = 32; st > 0; st >>= 1) {
        if (threadIdx.x < st) {
            sP[threadIdx.x] += sP[threadIdx.x + st];
            sM[threadIdx.x] += sM[threadIdx.x + st];
        }
        __syncthreads();
    }
    if (threadIdx.x == 0) {
        float M = sM[0];
        out[0] = (M > 0.0f) ? (sP[0] / (M + 1e-8f)) : 0.0f;
    }
}

// ---------------------------------------------------------------------------
extern "C" void kernel_launch(void* const* d_in, const int* in_sizes, int n_in,
                              void* d_out, int out_size) {
    const float* ps  = (const float*)d_in[0];   // (B, N)
    const float* pe  = (const float*)d_in[1];   // (B, N)
    const float* pcl = (const float*)d_in[2];   // (B, N, 2)
    const float* pcf = (const float*)d_in[3];   // (B, N)
    const float* gt  = (const float*)d_in[4];   // (B, K, 3)
    float* out = (float*)d_out;

    fused_topk_kernel<<<BB * QT, NTHR>>>(ps, pe, pcl, gt);
    merge_match_kernel<<<BB, NTHR>>>(ps, pe, pcl, pcf, gt);
    finalize_kernel<<<1, BB>>>(out);
}

// round 7
// speedup vs baseline: 2.3254x; 2.3254x over previous
#include <cuda_runtime.h>
#include <math.h>
#include <float.h>

#define BB 64
#define NN 32768
#define CC 2
#define KK 10
#define QTA 8                  // chunks per row, kernel A
#define CHA (NN / QTA)         // 4096
#define WSEG (CHA / 8)         // 512 columns per warp segment
#define NSEG (QTA * 8)         // 64 segments per row
#define QTB 8                  // chunks per row, kernel B
#define CHB (NN / QTB)         // 4096
#define CAP 2048               // candidate pool capacity per (b,row)
#define FULLM 0xffffffffu
#define MAXC 0x7fffffff

// fast sigmoid for cost scanning (identical instruction sequence in A and B)
static __device__ __forceinline__ float fsig(float x) {
    return __fdividef(1.0f, 1.0f + __expf(-x));
}
// accurate versions for the final loss terms
static __device__ __forceinline__ float sigmoidf_(float x) {
    return 1.0f / (1.0f + expf(-x));
}
static __device__ __forceinline__ float softplusf_(float x) {
    return fmaxf(x, 0.0f) + log1pf(expf(-fabsf(x)));
}

__device__ float g_segmin[BB * KK * NSEG];
__device__ int   g_cnt[BB * KK];
__device__ float g_cval[BB * KK * CAP];
__device__ int   g_ccol[BB * KK * CAP];
__device__ float g_bpart[BB];
__device__ float g_bm[BB];

// ---------------------------------------------------------------------------
// load per-row constants (shifted-cost form): v = s*ms + e*me + h0 + clm*dh
// ---------------------------------------------------------------------------
static __device__ __forceinline__ void load_rowconsts(
        const float* __restrict__ gt, int b,
        float* ms, float* me, float* clm, float* ck, bool* pres) {
#pragma unroll
    for (int k = 0; k < KK; k++) {
        const float* g = gt + (size_t)(b * KK + k) * 3;
        float a = g[0], c = g[1], d = g[2];
        bool p = !((a != a) || (c != c) || (d != d));
        pres[k] = p;
        if (p) {
            int ci = (int)d;
            ci = ci < 0 ? 0 : (ci > CC - 1 ? CC - 1 : ci);
            ms[k] = -2.0f * a;
            me[k] = -2.0f * c;
            clm[k] = (ci == 1) ? 1.0f : 0.0f;
            ck[k] = fmaf(a, a, c * c);
        } else {
            ms[k] = 0.0f; me[k] = 0.0f; clm[k] = 0.0f; ck[k] = 0.0f;
        }
    }
}

// ---------------------------------------------------------------------------
// Kernel A: per-(row, 512-col segment) minimum of shifted cost. No smem tile,
// no collectives in the loop — 10 independent FMA+min chains per lane.
// ---------------------------------------------------------------------------
__global__ __launch_bounds__(256) void minseg_kernel(
        const float* __restrict__ ps,
        const float* __restrict__ pe,
        const float* __restrict__ pcl,
        const float* __restrict__ gt) {
    int b = blockIdx.x >> 3;
    int chunk = blockIdx.x & (QTA - 1);
    if (chunk == 0 && threadIdx.x < KK) g_cnt[b * KK + threadIdx.x] = 0;

    int w = threadIdx.x >> 5;
    int lane = threadIdx.x & 31;

    float ms[KK], me[KK], clm[KK], ck[KK]; bool pres[KK];
    load_rowconsts(gt, b, ms, me, clm, ck, pres);

    float rmin[KK];
#pragma unroll
    for (int k = 0; k < KK; k++) rmin[k] = FLT_MAX;

    const float4* ps4  = reinterpret_cast<const float4*>(ps + (size_t)b * NN);
    const float4* pe4  = reinterpret_cast<const float4*>(pe + (size_t)b * NN);
    const float4* pcl4 = reinterpret_cast<const float4*>(pcl + (size_t)b * NN * 2);
    int cb4 = (chunk * CHA + w * WSEG) >> 2;

#pragma unroll
    for (int q = 0; q < WSEG / 128; q++) {      // 4 iters, 4 cols/lane each
        int i4 = cb4 + q * 32 + lane;
        float4 A  = ps4[i4];
        float4 Bq = pe4[i4];
        float4 L0 = pcl4[2 * i4];
        float4 L1 = pcl4[2 * i4 + 1];
        float sv[4]  = {A.x, A.y, A.z, A.w};
        float ev[4]  = {Bq.x, Bq.y, Bq.z, Bq.w};
        float c0v[4] = {L0.x, L0.z, L1.x, L1.z};
        float c1v[4] = {L0.y, L0.w, L1.y, L1.w};
#pragma unroll
        for (int j = 0; j < 4; j++) {
            float s  = fsig(sv[j]);
            float e  = fsig(ev[j]);
            float c0 = fsig(c0v[j]);
            float c1 = fsig(c1v[j]);
            float base = fmaf(s, s, fmaf(e, e, fmaf(c0, c0, fmaf(c1, c1, 1.0f))));
            float h0 = base - 2.0f * c0;
            float dh = 2.0f * (c0 - c1);
#pragma unroll
            for (int k = 0; k < KK; k++) {
                float v = fmaf(s, ms[k], fmaf(e, me[k], fmaf(clm[k], dh, h0)));
                rmin[k] = fminf(rmin[k], v);
            }
        }
    }

    // warp min-reduce per row, lane 0 stores segment minimum
#pragma unroll
    for (int k = 0; k < KK; k++) {
        float m = rmin[k];
#pragma unroll
        for (int o = 16; o; o >>= 1) m = fminf(m, __shfl_xor_sync(FULLM, m, o));
        if (lane == 0) g_segmin[(b * KK + k) * NSEG + chunk * 8 + w] = m;
    }
}

// ---------------------------------------------------------------------------
// Kernel B: tau = 10th-smallest segment min per row, then rescan and append
// all items with v <= tau to the per-row candidate pool (rare atomics).
// ---------------------------------------------------------------------------
__global__ __launch_bounds__(320) void filter_kernel(
        const float* __restrict__ ps,
        const float* __restrict__ pe,
        const float* __restrict__ pcl,
        const float* __restrict__ gt) {
    __shared__ float stau[KK];

    int b = blockIdx.x >> 3;
    int chunk = blockIdx.x & (QTB - 1);
    int w = threadIdx.x >> 5;
    int lane = threadIdx.x & 31;

    float ms[KK], me[KK], clm[KK], ck[KK]; bool pres[KK];
    load_rowconsts(gt, b, ms, me, clm, ck, pres);

    // ---- tau per row: 10th smallest of 64 segment minima ----
    if (w < KK) {
        if (!pres[w]) {
            if (lane == 0) stau[w] = -FLT_MAX;   // absent: never pass
        } else {
            int base = (b * KK + w) * NSEG;
            float v0 = g_segmin[base + lane];
            float v1 = g_segmin[base + 32 + lane];
            float tau = FLT_MAX;
#pragma unroll
            for (int r = 0; r < KK; r++) {
                int sl = (v1 < v0) ? 1 : 0;
                float mv = fminf(v0, v1);
                int src = lane;
#pragma unroll
                for (int o = 16; o; o >>= 1) {
                    float ov = __shfl_xor_sync(FULLM, mv, o);
                    int   os = __shfl_xor_sync(FULLM, src, o);
                    if (ov < mv || (ov == mv && os < src)) { mv = ov; src = os; }
                }
                if (lane == src) { if (sl) v1 = FLT_MAX; else v0 = FLT_MAX; }
                tau = mv;
            }
            if (lane == 0) stau[w] = tau;
        }
    }
    __syncthreads();

    float tk[KK];
#pragma unroll
    for (int k = 0; k < KK; k++) tk[k] = stau[k];

    const float4* ps4  = reinterpret_cast<const float4*>(ps + (size_t)b * NN);
    const float4* pe4  = reinterpret_cast<const float4*>(pe + (size_t)b * NN);
    const float4* pcl4 = reinterpret_cast<const float4*>(pcl + (size_t)b * NN * 2);
    int cb4 = (chunk * CHB) >> 2;

    for (int i4 = threadIdx.x; i4 < CHB / 4; i4 += 320) {
        int gi4 = cb4 + i4;
        float4 A  = ps4[gi4];
        float4 Bq = pe4[gi4];
        float4 L0 = pcl4[2 * gi4];
        float4 L1 = pcl4[2 * gi4 + 1];
        float sv[4]  = {A.x, A.y, A.z, A.w};
        float ev[4]  = {Bq.x, Bq.y, Bq.z, Bq.w};
        float c0v[4] = {L0.x, L0.z, L1.x, L1.z};
        float c1v[4] = {L0.y, L0.w, L1.y, L1.w};
#pragma unroll
        for (int j = 0; j < 4; j++) {
            float s  = fsig(sv[j]);
            float e  = fsig(ev[j]);
            float c0 = fsig(c0v[j]);
            float c1 = fsig(c1v[j]);
            float base = fmaf(s, s, fmaf(e, e, fmaf(c0, c0, fmaf(c1, c1, 1.0f))));
            float h0 = base - 2.0f * c0;
            float dh = 2.0f * (c0 - c1);
            int col = gi4 * 4 + j;
#pragma unroll
            for (int k = 0; k < KK; k++) {
                float v = fmaf(s, ms[k], fmaf(e, me[k], fmaf(clm[k], dh, h0)));
                if (v <= tk[k]) {                 // rare
                    int pos = atomicAdd(&g_cnt[b * KK + k], 1);
                    if (pos < CAP) {
                        g_cval[(b * KK + k) * CAP + pos] = v + ck[k];  // true cost
                        g_ccol[(b * KK + k) * CAP + pos] = col;
                    }
                }
            }
        }
    }
}

// ---------------------------------------------------------------------------
// Warp-collective: merge up to 64 candidates + current distributed top-10
// (lane j < 10 holds j-th best). Lexicographic (val, col) ascending.
// ---------------------------------------------------------------------------
static __device__ __forceinline__ void merge10(float& lv, int& lc, int cnt,
                                               const float* __restrict__ bv,
                                               const int* __restrict__ bc,
                                               int lane) {
    float v0 = (lane < cnt) ? bv[lane] : FLT_MAX;
    int   c0 = (lane < cnt) ? bc[lane] : MAXC;
    float v1 = (lane + 32 < cnt) ? bv[lane + 32] : FLT_MAX;
    int   c1 = (lane + 32 < cnt) ? bc[lane + 32] : MAXC;
    float v2 = lv;  // lanes >= 10 hold FLT_MAX
    int   c2 = lc;
    float nv = FLT_MAX; int nc = MAXC;
#pragma unroll
    for (int r = 0; r < KK; r++) {
        float mv = v0; int mc = c0; int sl = 0;
        if (v1 < mv || (v1 == mv && c1 < mc)) { mv = v1; mc = c1; sl = 1; }
        if (v2 < mv || (v2 == mv && c2 < mc)) { mv = v2; mc = c2; sl = 2; }
        int src = lane;
#pragma unroll
        for (int o = 16; o; o >>= 1) {
            float ov = __shfl_xor_sync(FULLM, mv, o);
            int   oc = __shfl_xor_sync(FULLM, mc, o);
            int   os = __shfl_xor_sync(FULLM, src, o);
            if (ov < mv || (ov == mv && oc < mc)) { mv = ov; mc = oc; src = os; }
        }
        if (lane == src) {
            if (sl == 0)      { v0 = FLT_MAX; c0 = MAXC; }
            else if (sl == 1) { v1 = FLT_MAX; c1 = MAXC; }
            else              { v2 = FLT_MAX; c2 = MAXC; }
        }
        if (lane == r) { nv = mv; nc = mc; }
    }
    lv = nv; lc = nc;
}

// ---------------------------------------------------------------------------
// Kernel C: per-batch candidate merge + warp-parallel greedy match + losses
// ---------------------------------------------------------------------------
__global__ __launch_bounds__(320) void merge_match_kernel(
        const float* __restrict__ ps,
        const float* __restrict__ pe,
        const float* __restrict__ pcl,
        const float* __restrict__ pcf,
        const float* __restrict__ gt) {
    __shared__ float sval[KK * KK];
    __shared__ int   scol[KK * KK];
    __shared__ float s_fs[KK], s_fe[KK];
    __shared__ int   s_cli[KK];
    __shared__ int   s_mk[KK], s_mcol[KK];
    __shared__ int   s_nm;
    __shared__ float s_loss[KK];

    int b = blockIdx.x;
    int w = threadIdx.x >> 5;
    int lane = threadIdx.x & 31;

    if (threadIdx.x < KK) {
        const float* g = gt + (size_t)(b * KK + threadIdx.x) * 3;
        float a = g[0], c = g[1], d = g[2];
        bool p = !((a != a) || (c != c) || (d != d));
        s_fs[threadIdx.x] = (a != a) ? 0.0f : a;
        s_fe[threadIdx.x] = (c != c) ? 0.0f : c;
        d = (d != d) ? 0.0f : d;
        int ci = (int)d;
        ci = ci < 0 ? 0 : (ci > CC - 1 ? CC - 1 : ci);
        s_cli[threadIdx.x] = p ? ci : -1;
    }

    // ---- top-10 per row from candidate pool ----
    {
        const float* g = gt + (size_t)(b * KK + w) * 3;
        float a = g[0], c = g[1], d = g[2];
        bool p = !((a != a) || (c != c) || (d != d));
        int cn = p ? g_cnt[b * KK + w] : 0;
        if (cn > CAP) cn = CAP;
        float lv = FLT_MAX; int lc = MAXC;
        const float* vptr = g_cval + (size_t)(b * KK + w) * CAP;
        const int*   cptr = g_ccol + (size_t)(b * KK + w) * CAP;
        for (int base = 0; base < cn; base += 64) {
            int m = cn - base; if (m > 64) m = 64;
            merge10(lv, lc, m, vptr + base, cptr + base, lane);
        }
        if (lane < KK) { sval[w * KK + lane] = lv; scol[w * KK + lane] = lc; }
    }
    __syncthreads();

    // ---- warp-parallel greedy match (warp 0, lane k owns row k) ----
    if (w == 0) {
        bool active = (lane < KK) && (s_cli[lane] >= 0);
        int ptr = 0;
        int usedc[KK];
        int nused = 0;
        int nm = 0;
        for (int it = 0; it < KK; it++) {
            float myv = FLT_MAX; int mycol = MAXC;
            if (active) {
                while (ptr < KK) {
                    int col = scol[lane * KK + ptr];
                    bool isused = false;
                    for (int u = 0; u < nused; u++) isused |= (usedc[u] == col);
                    if (!isused) { myv = sval[lane * KK + ptr]; mycol = col; break; }
                    ptr++;
                }
            }
            float bvv = myv; int brow = lane; int bcol = mycol;
#pragma unroll
            for (int o = 16; o; o >>= 1) {
                float ov = __shfl_xor_sync(FULLM, bvv, o);
                int   orw = __shfl_xor_sync(FULLM, brow, o);
                int   ocl = __shfl_xor_sync(FULLM, bcol, o);
                if (ov < bvv || (ov == bvv && orw < brow)) { bvv = ov; brow = orw; bcol = ocl; }
            }
            if (bvv == FLT_MAX) break;
            usedc[nused++] = bcol;
            if (lane == brow) active = false;
            if (bvv < 0.5e6f) {
                if (lane == 0) { s_mk[nm] = brow; s_mcol[nm] = bcol; }
                nm++;
            }
        }
        if (lane == 0) s_nm = nm;
    }
    __syncthreads();

    // ---- exact loss terms in parallel ----
    int nm = s_nm;
    if (threadIdx.x < KK) {
        float part = 0.0f;
        if (threadIdx.x < nm) {
            int k = s_mk[threadIdx.x];
            int col = s_mcol[threadIdx.x];
            size_t idx = (size_t)b * NN + col;
            float ss = sigmoidf_(ps[idx]);
            float se = sigmoidf_(pe[idx]);
            float gs = s_fs[k], ge = s_fe[k];
            float dls = ss - gs, dle = se - ge;
            part = dls * dls + dle * dle;                            // loc
            float l0 = pcl[idx * 2], l1 = pcl[idx * 2 + 1];
            part += (s_cli[k] == 0) ? (softplusf_(-l0) + softplusf_(l1))
                                    : (softplusf_(l0) + softplusf_(-l1));  // class
            float a1 = fminf(ss, se), b1 = fmaxf(ss, se);
            float a2 = fminf(gs, ge), b2 = fmaxf(gs, ge);
            float inter = fmaxf(0.0f, fminf(b1, b2) - fmaxf(a1, a2));
            float uni = fmaxf(1e-8f, fmaxf(b1, b2) - fminf(a1, a2));
            float iou = inter / uni;
            float dcf = sigmoidf_(pcf[idx]) - iou;
            part += dcf * dcf;                                       // conf
        }
        s_loss[threadIdx.x] = part;
    }
    __syncthreads();

    if (threadIdx.x == 0) {
        float tot = 0.0f;
#pragma unroll
        for (int j = 0; j < KK; j++) tot += s_loss[j];
        g_bpart[b] = tot;
        g_bm[b] = (float)nm;
    }
}

// ---------------------------------------------------------------------------
// Kernel D: final reduction over batches
// ---------------------------------------------------------------------------
__global__ void finalize_kernel(float* __restrict__ out) {
    __shared__ float sP[BB], sM[BB];
    sP[threadIdx.x] = g_bpart[threadIdx.x];
    sM[threadIdx.x] = g_bm[threadIdx.x];
    __syncthreads();
    for (int st = 32; st > 0; st >>= 1) {
        if (threadIdx.x < st) {
            sP[threadIdx.x] += sP[threadIdx.x + st];
            sM[threadIdx.x] += sM[threadIdx.x + st];
        }
        __syncthreads();
    }
    if (threadIdx.x == 0) {
        float M = sM[0];
        out[0] = (M > 0.0f) ? (sP[0] / (M + 1e-8f)) : 0.0f;
    }
}

// ---------------------------------------------------------------------------
extern "C" void kernel_launch(void* const* d_in, const int* in_sizes, int n_in,
                              void* d_out, int out_size) {
    const float* ps  = (const float*)d_in[0];   // (B, N)
    const float* pe  = (const float*)d_in[1];   // (B, N)
    const float* pcl = (const float*)d_in[2];   // (B, N, 2)
    const float* pcf = (const float*)d_in[3];   // (B, N)
    const float* gt  = (const float*)d_in[4];   // (B, K, 3)
    float* out = (float*)d_out;

    minseg_kernel<<<BB * QTA, 256>>>(ps, pe, pcl, gt);
    filter_kernel<<<BB * QTB, 320>>>(ps, pe, pcl, gt);
    merge_match_kernel<<<BB, 320>>>(ps, pe, pcl, pcf, gt);
    finalize_kernel<<<1, BB>>>(out);
}